// round 15
// baseline (speedup 1.0000x reference)
#include <cuda_runtime.h>
#include <cuda_bf16.h>
#include <math.h>
#include <stdint.h>

#define NN 100000
#define EE 3200000
#define DD 128
#define H2 256
#define LL 4
#define GG 1000
#define CC 10
#define BN_EPS 1e-5f
#define NPART 98   // ceil(NN/1024)

// -------- scratch --------
__device__ float d_agg[(size_t)NN * DD];
__device__ float d_y1 [(size_t)NN * H2];
__device__ float d_y2 [(size_t)NN * DD];
__device__ float d_ge [(size_t)GG * DD];
__device__ float d_gm1[(size_t)GG * DD];
__device__ float d_stats[2 * H2];      // zero-init; finalize self-cleans
__device__ float d_scale[H2];
__device__ float d_shift[H2];
// CSR scratch
__device__ int d_counts[NN];
__device__ int d_off[NN + 1];
__device__ int d_cur[NN];
__device__ int d_csr[EE];
__device__ int d_part[NPART];
// pre-packed weights, bf16x2 fragment order (hi/mid): per layer 16384 u32 each
__device__ uint32_t d_pW1Hi[4 * 16384];
__device__ uint32_t d_pW1Md[4 * 16384];
__device__ uint32_t d_pW2Hi[4 * 16384];
__device__ uint32_t d_pW2Md[4 * 16384];

// ================= bf16 helpers =================
static __device__ __forceinline__ void split2(float v0, float v1,
                                              uint32_t& hi, uint32_t& md) {
    __nv_bfloat16 h0 = __float2bfloat16_rn(v0);
    __nv_bfloat16 h1 = __float2bfloat16_rn(v1);
    float m0 = v0 - __bfloat162float(h0);
    float m1 = v1 - __bfloat162float(h1);
    __nv_bfloat162 hp = __halves2bfloat162(h0, h1);       // .x = lo half = k even
    __nv_bfloat162 mp = __floats2bfloat162_rn(m0, m1);
    hi = *reinterpret_cast<uint32_t*>(&hp);
    md = *reinterpret_cast<uint32_t*>(&mp);
}
static __device__ __forceinline__ void mma16(float* c, const uint32_t* a, const uint32_t* b) {
    asm volatile(
        "mma.sync.aligned.m16n8k16.row.col.f32.bf16.bf16.f32 "
        "{%0,%1,%2,%3}, {%4,%5,%6,%7}, {%8,%9}, {%0,%1,%2,%3};"
        : "+f"(c[0]), "+f"(c[1]), "+f"(c[2]), "+f"(c[3])
        : "r"(a[0]), "r"(a[1]), "r"(a[2]), "r"(a[3]), "r"(b[0]), "r"(b[1]));
}

// ======== W pre-pack (ALL layers/tensors in ONE launch) ========
__global__ void packAll_kernel(const float* __restrict__ W1,
                               const float* __restrict__ W2) {
    int which = blockIdx.y;
    int l = which >> 1;
    int isW2 = which & 1;
    int K  = isW2 ? H2 : DD;
    int NC = isW2 ? DD : H2;
    const float* W = (isW2 ? W2 : W1) + (size_t)l * DD * H2;
    uint32_t* pHi = (isW2 ? d_pW2Hi : d_pW1Hi) + (size_t)l * 16384;
    uint32_t* pMd = (isW2 ? d_pW2Md : d_pW1Md) + (size_t)l * 16384;

    int idx = blockIdx.x * 256 + threadIdx.x;
    if (idx >= (K / 2) * NC) return;
    int k2 = idx / NC, n = idx % NC;
    int k = k2 * 2;
    float v0 = W[(size_t)k * NC + n];
    float v1 = W[(size_t)(k + 1) * NC + n];
    uint32_t hi, md;
    split2(v0, v1, hi, md);
    int colblk = n >> 7, nloc = n & 127;
    int ktile = k >> 5, kin32 = k & 31;
    int k16 = kin32 >> 4, kin16 = kin32 & 15;
    int kpair = kin16 >> 1;
    int j = kpair >> 2;
    int lane = ((nloc & 7) << 2) | (kpair & 3);
    int n8 = nloc >> 3;
    int KT = K / 32;
    size_t o = (size_t)(colblk * KT + ktile) * 2048 +
               (size_t)((k16 * 16 + n8) * 32 + lane) * 2 + j;
    pHi[o] = hi;
    pMd[o] = md;
}

// ====== bf16 2-split x3 MMA GEMM: no register staging, 2 CTAs/SM for overlap ======
// MODE 1: a = relu(A*scale[k]+shift[k]);  MODE 2: a = A
template <int K, int NC, int MODE>
__global__ __launch_bounds__(256, 2) void mma_gemm_kernel(
    const float* __restrict__ A,
    const uint4* __restrict__ pWH,
    const uint4* __restrict__ pWM,
    const float* __restrict__ bias,
    float* __restrict__ C, int M)
{
    constexpr int KT = K / 32;
    extern __shared__ uint32_t smu[];
    __shared__ float s_bias[128];
    __shared__ float sScale[256];
    __shared__ float sShift[256];
    __shared__ float s_sum[128];
    __shared__ float s_sq[128];

    int tid = threadIdx.x;
    int lane = tid & 31;
    int w = tid >> 5;
    int wm = w & 3;
    int wn = w >> 2;
    int rowBase = blockIdx.x * 128;
    int colBase = blockIdx.y * 128;

    if (tid < 128) { s_bias[tid] = bias[colBase + tid]; s_sum[tid] = 0.f; s_sq[tid] = 0.f; }
    if (MODE == 1) {
        for (int c = tid; c < K; c += 256) { sScale[c] = d_scale[c]; sShift[c] = d_shift[c]; }
    }
    __syncthreads();

    float acc[2][8][4];
#pragma unroll
    for (int i = 0; i < 2; i++)
#pragma unroll
        for (int t = 0; t < 8; t++)
#pragma unroll
            for (int j = 0; j < 4; j++) acc[i][t][j] = 0.f;

    int kpairT = lane & 7;
    int k16T   = (w >> 2) & 1;
    int mLow   = (((lane >> 4) & 1) << 3) | ((w & 3) << 1) | ((lane >> 3) & 1);
    int jA     = ((kpairT >> 2) << 1) | ((lane >> 4) & 1);
    int laneA  = (((mLow & 7)) << 2) | (kpairT & 3);

    // direct LDG -> (BN) -> split -> STS  (no register staging; 2 CTAs/SM hide latency)
    auto ldgstsA = [&](int k0, int buf) {
        uint32_t* aHi = smu + buf * 8192;
        uint32_t* aMd = aHi + 2048;
        int kc0 = (k16T << 4) + (kpairT << 1);
        int kk = k0 + kc0;
        float2 v[8];
#pragma unroll
        for (int e = 0; e < 8; e++) {
            int m = (e << 4) | mLow;
            v[e] = (rowBase + m < M)
                ? *reinterpret_cast<const float2*>(A + (size_t)(rowBase + m) * K + kk)
                : make_float2(0.f, 0.f);
        }
#pragma unroll
        for (int e = 0; e < 8; e++) {
            float v0 = v[e].x, v1 = v[e].y;
            if (MODE == 1) {
                int kc = k0 + kc0;
                v0 = fmaxf(v0 * sScale[kc] + sShift[kc], 0.f);
                v1 = fmaxf(v1 * sScale[kc + 1] + sShift[kc + 1], 0.f);
            }
            uint32_t hi, md;
            split2(v0, v1, hi, md);
            int idx = ((k16T * 8 + e) * 32 + laneA) * 4 + jA;
            aHi[idx] = hi;
            aMd[idx] = md;
        }
    };
    auto ldgstsB = [&](int kt, int buf) {
        size_t blkOff = (size_t)(blockIdx.y * KT + kt) * 512;
        uint4* bHi = reinterpret_cast<uint4*>(smu + buf * 8192 + 4096);
        uint4* bMd = reinterpret_cast<uint4*>(smu + buf * 8192 + 6144);
        uint4 h0 = pWH[blkOff + tid];
        uint4 h1 = pWH[blkOff + tid + 256];
        uint4 m0 = pWM[blkOff + tid];
        uint4 m1 = pWM[blkOff + tid + 256];
        bHi[tid] = h0; bHi[tid + 256] = h1;
        bMd[tid] = m0; bMd[tid + 256] = m1;
    };

    // prologue
    ldgstsA(0, 0);
    ldgstsB(0, 0);
    __syncthreads();

    for (int kt = 0; kt < KT; kt++) {
        int buf = kt & 1;
        uint32_t* aHi = smu + buf * 8192;
        uint32_t* aMd = aHi + 2048;
        uint32_t* bHi = smu + buf * 8192 + 4096;
        uint32_t* bMd = smu + buf * 8192 + 6144;
#pragma unroll
        for (int s = 0; s < 2; s++) {
            uint32_t ah[2][4], am[2][4], bh[8][2], bm[8][2];
#pragma unroll
            for (int i = 0; i < 2; i++) {
                int base = ((s * 8 + (wm * 2 + i)) * 32 + lane) * 4;
                *reinterpret_cast<uint4*>(ah[i]) = *reinterpret_cast<const uint4*>(aHi + base);
                *reinterpret_cast<uint4*>(am[i]) = *reinterpret_cast<const uint4*>(aMd + base);
            }
#pragma unroll
            for (int t = 0; t < 8; t++) {
                int base = ((s * 16 + (wn * 8 + t)) * 32 + lane) * 2;
                *reinterpret_cast<uint2*>(bh[t]) = *reinterpret_cast<const uint2*>(bHi + base);
                *reinterpret_cast<uint2*>(bm[t]) = *reinterpret_cast<const uint2*>(bMd + base);
            }
#pragma unroll
            for (int i = 0; i < 2; i++)
#pragma unroll
                for (int t = 0; t < 8; t++) {
                    mma16(acc[i][t], ah[i], bh[t]);
                    mma16(acc[i][t], ah[i], bm[t]);
                    mma16(acc[i][t], am[i], bh[t]);
                }
        }
        // single barrier per ktile: writes go to buf^1, whose last readers
        // finished before the PREVIOUS barrier.
        if (kt + 1 < KT) {
            ldgstsA((kt + 1) * 32, buf ^ 1);
            ldgstsB(kt + 1, buf ^ 1);
            __syncthreads();
        }
    }

    // epilogue + fused column stats
    int g = lane >> 2, tq = lane & 3;
    float csum[16], csq[16];
#pragma unroll
    for (int t = 0; t < 16; t++) { csum[t] = 0.f; csq[t] = 0.f; }

#pragma unroll
    for (int i = 0; i < 2; i++) {
        int r0 = rowBase + wm * 32 + i * 16 + g;
#pragma unroll
        for (int t = 0; t < 8; t++) {
            int cloc = wn * 64 + t * 8 + 2 * tq;
            int cg = colBase + cloc;
            float b0 = s_bias[cloc], b1 = s_bias[cloc + 1];
            if (r0 < M) {
                float y0 = acc[i][t][0] + b0, y1 = acc[i][t][1] + b1;
                *reinterpret_cast<float2*>(C + (size_t)r0 * NC + cg) = make_float2(y0, y1);
                csum[2 * t] += y0; csq[2 * t] += y0 * y0;
                csum[2 * t + 1] += y1; csq[2 * t + 1] += y1 * y1;
            }
            if (r0 + 8 < M) {
                float y2 = acc[i][t][2] + b0, y3 = acc[i][t][3] + b1;
                *reinterpret_cast<float2*>(C + (size_t)(r0 + 8) * NC + cg) = make_float2(y2, y3);
                csum[2 * t] += y2; csq[2 * t] += y2 * y2;
                csum[2 * t + 1] += y3; csq[2 * t + 1] += y3 * y3;
            }
        }
    }
#pragma unroll
    for (int t = 0; t < 8; t++) {
        int cloc = wn * 64 + t * 8 + 2 * tq;
        atomicAdd(&s_sum[cloc], csum[2 * t]);
        atomicAdd(&s_sq[cloc], csq[2 * t]);
        atomicAdd(&s_sum[cloc + 1], csum[2 * t + 1]);
        atomicAdd(&s_sq[cloc + 1], csq[2 * t + 1]);
    }
    __syncthreads();
    if (tid < 128) {
        atomicAdd(&d_stats[colBase + tid], s_sum[tid]);
        atomicAdd(&d_stats[NC + colBase + tid], s_sq[tid]);
    }
}

// ================= CSR build =================
__global__ void hist_kernel(const int* __restrict__ dst) {
    int e = blockIdx.x * blockDim.x + threadIdx.x;
    if (e < EE) atomicAdd(&d_counts[dst[e]], 1);
}

__global__ void scan_block_kernel() {
    __shared__ int sm[1024];
    int b = blockIdx.x, t = threadIdx.x;
    int i = b * 1024 + t;
    sm[t] = (i < NN) ? d_counts[i] : 0;
    __syncthreads();
    for (int s = 1; s < 1024; s <<= 1) {
        int a = (t >= s) ? sm[t - s] : 0;
        __syncthreads();
        sm[t] += a;
        __syncthreads();
    }
    if (i < NN) d_off[i + 1] = sm[t];
    if (t == 1023) d_part[b] = sm[1023];
}

__global__ void scan_part_kernel() {
    __shared__ int sm[128];
    int t = threadIdx.x;
    sm[t] = (t < NPART) ? d_part[t] : 0;
    __syncthreads();
    for (int s = 1; s < 128; s <<= 1) {
        int a = (t >= s) ? sm[t - s] : 0;
        __syncthreads();
        sm[t] += a;
        __syncthreads();
    }
    if (t < NPART) d_part[t] = sm[t];
    if (t == 0) { d_off[0] = 0; d_cur[0] = 0; }
}

__global__ void scan_add_kernel() {
    int b = blockIdx.x, t = threadIdx.x;
    int i = b * 1024 + t;
    if (i < NN) {
        int add = (b > 0) ? d_part[b - 1] : 0;
        int v = d_off[i + 1] + add;
        d_off[i + 1] = v;
        if (i + 1 < NN) d_cur[i + 1] = v;
    }
}

__global__ void fill_kernel(const int* __restrict__ src, const int* __restrict__ dst) {
    int e = blockIdx.x * blockDim.x + threadIdx.x;
    if (e < EE) {
        int d = dst[e];
        int p = atomicAdd(&d_cur[d], 1);
        d_csr[p] = src[e];
    }
}

// ========== aggregation with optional fused BN+relu on the gathered input ==========
template <int MODE>
__global__ void aggregate_kernel(const float* __restrict__ h,
                                 const float* __restrict__ epsp) {
    int gt = blockIdx.x * blockDim.x + threadIdx.x;
    int n = gt >> 5;
    int lane = gt & 31;
    if (n >= NN) return;
    float4 sc, sf;
    if (MODE == 1) {
        sc = *reinterpret_cast<const float4*>(d_scale + lane * 4);
        sf = *reinterpret_cast<const float4*>(d_shift + lane * 4);
    }
    int beg = d_off[n], end = d_off[n + 1];
    float4 acc = make_float4(0.f, 0.f, 0.f, 0.f);
    const float* hl = h + (size_t)lane * 4;

    auto fetch = [&](int node) -> float4 {
        float4 v = *reinterpret_cast<const float4*>(hl + (size_t)node * DD);
        if (MODE == 1) {
            v.x = fmaxf(v.x * sc.x + sf.x, 0.f);
            v.y = fmaxf(v.y * sc.y + sf.y, 0.f);
            v.z = fmaxf(v.z * sc.z + sf.z, 0.f);
            v.w = fmaxf(v.w * sc.w + sf.w, 0.f);
        }
        return v;
    };

    int i = beg;
    for (; i + 4 <= end; i += 4) {
        float4 v0 = fetch(d_csr[i]);
        float4 v1 = fetch(d_csr[i + 1]);
        float4 v2 = fetch(d_csr[i + 2]);
        float4 v3 = fetch(d_csr[i + 3]);
        acc.x += (v0.x + v1.x) + (v2.x + v3.x);
        acc.y += (v0.y + v1.y) + (v2.y + v3.y);
        acc.z += (v0.z + v1.z) + (v2.z + v3.z);
        acc.w += (v0.w + v1.w) + (v2.w + v3.w);
    }
    for (; i < end; i++) {
        float4 v0 = fetch(d_csr[i]);
        acc.x += v0.x; acc.y += v0.y; acc.z += v0.z; acc.w += v0.w;
    }
    float e = 1.0f + epsp[0];
    float4 self = fetch(n);
    acc.x += e * self.x; acc.y += e * self.y;
    acc.z += e * self.z; acc.w += e * self.w;
    *reinterpret_cast<float4*>(d_agg + (size_t)n * DD + lane * 4) = acc;
}

// ================= pool with fused BN+relu (reads y2) =================
__global__ void pool_kernel(const float* __restrict__ y2,
                            const int* __restrict__ batch) {
    int gt = blockIdx.x * blockDim.x + threadIdx.x;
    int n = gt >> 5;
    int lane = gt & 31;
    if (n >= NN) return;
    float4 sc = *reinterpret_cast<const float4*>(d_scale + lane * 4);
    float4 sf = *reinterpret_cast<const float4*>(d_shift + lane * 4);
    int g = batch[n];
    float4 v = *reinterpret_cast<const float4*>(y2 + (size_t)n * DD + lane * 4);
    v.x = fmaxf(v.x * sc.x + sf.x, 0.f);
    v.y = fmaxf(v.y * sc.y + sf.y, 0.f);
    v.z = fmaxf(v.z * sc.z + sf.z, 0.f);
    v.w = fmaxf(v.w * sc.w + sf.w, 0.f);
    atomicAdd(reinterpret_cast<float4*>(d_ge + (size_t)g * DD + lane * 4), v);
}

// ================= SIMT GEMM (head only; fused stats) =================
template <int K, int NC, int MODE>
__global__ __launch_bounds__(256, 2) void gemm128_kernel(
    const float* __restrict__ A,
    const float* __restrict__ W,
    const float* __restrict__ bias,
    float* __restrict__ C, int M)
{
    constexpr int BM = 128, BN = 128, BK = 16;
    constexpr int KT = K / BK;
    __shared__ float As[2][BK][BM + 4];
    __shared__ float Bs[2][BK][BN];
    __shared__ float s_sum[BN];
    __shared__ float s_sq[BN];

    int tid = threadIdx.x;
    int tr = tid >> 4;
    int tc = tid & 15;
    int rowBase = blockIdx.x * BM;
    int colBase = blockIdx.y * BN;

    float acc[8][8];
#pragma unroll
    for (int i = 0; i < 8; i++)
#pragma unroll
        for (int j = 0; j < 8; j++) acc[i][j] = 0.f;

    float4 a_reg[2], b_reg[2];

    auto loadA = [&](int k0, int q) -> float4 {
        int fIdx = tid + q * 256;
        int m = fIdx >> 2;
        int kq = (fIdx & 3) << 2;
        int gr = rowBase + m;
        float4 v = make_float4(0.f, 0.f, 0.f, 0.f);
        if (gr < M) v = *reinterpret_cast<const float4*>(A + (size_t)gr * K + k0 + kq);
        return v;
    };
    auto loadB = [&](int k0, int q) -> float4 {
        int fIdx = tid + q * 256;
        int kk = fIdx >> 5;
        int n4 = (fIdx & 31) << 2;
        return *reinterpret_cast<const float4*>(W + (size_t)(k0 + kk) * NC + colBase + n4);
    };
    auto storeA = [&](int buf, int q, float4 v) {
        int fIdx = tid + q * 256;
        int m = fIdx >> 2;
        int kq = (fIdx & 3) << 2;
        As[buf][kq + 0][m] = v.x;
        As[buf][kq + 1][m] = v.y;
        As[buf][kq + 2][m] = v.z;
        As[buf][kq + 3][m] = v.w;
    };
    auto storeB = [&](int buf, int q, float4 v) {
        int fIdx = tid + q * 256;
        int kk = fIdx >> 5;
        int n4 = (fIdx & 31) << 2;
        *reinterpret_cast<float4*>(&Bs[buf][kk][n4]) = v;
    };

    a_reg[0] = loadA(0, 0); a_reg[1] = loadA(0, 1);
    b_reg[0] = loadB(0, 0); b_reg[1] = loadB(0, 1);
    storeA(0, 0, a_reg[0]); storeA(0, 1, a_reg[1]);
    storeB(0, 0, b_reg[0]); storeB(0, 1, b_reg[1]);
    __syncthreads();

    for (int kt = 0; kt < KT; kt++) {
        int buf = kt & 1;
        if (kt + 1 < KT) {
            int k0 = (kt + 1) * BK;
            a_reg[0] = loadA(k0, 0); a_reg[1] = loadA(k0, 1);
            b_reg[0] = loadB(k0, 0); b_reg[1] = loadB(k0, 1);
        }
#pragma unroll
        for (int kk = 0; kk < BK; kk++) {
            float ra[8], rb[8];
            *reinterpret_cast<float4*>(ra)     = *reinterpret_cast<const float4*>(&As[buf][kk][tr * 8]);
            *reinterpret_cast<float4*>(ra + 4) = *reinterpret_cast<const float4*>(&As[buf][kk][tr * 8 + 4]);
            *reinterpret_cast<float4*>(rb)     = *reinterpret_cast<const float4*>(&Bs[buf][kk][tc * 8]);
            *reinterpret_cast<float4*>(rb + 4) = *reinterpret_cast<const float4*>(&Bs[buf][kk][tc * 8 + 4]);
#pragma unroll
            for (int i = 0; i < 8; i++)
#pragma unroll
                for (int j = 0; j < 8; j++) acc[i][j] += ra[i] * rb[j];
        }
        if (kt + 1 < KT) {
            storeA(buf ^ 1, 0, a_reg[0]); storeA(buf ^ 1, 1, a_reg[1]);
            storeB(buf ^ 1, 0, b_reg[0]); storeB(buf ^ 1, 1, b_reg[1]);
        }
        __syncthreads();
    }

    float bj[8];
#pragma unroll
    for (int j = 0; j < 8; j++) bj[j] = bias[colBase + tc * 8 + j];

    float csum[8], csq[8];
#pragma unroll
    for (int j = 0; j < 8; j++) { csum[j] = 0.f; csq[j] = 0.f; }

#pragma unroll
    for (int i = 0; i < 8; i++) {
        int gr = rowBase + tr * 8 + i;
        if (gr < M) {
            float y[8];
#pragma unroll
            for (int j = 0; j < 8; j++) {
                y[j] = acc[i][j] + bj[j];
                csum[j] += y[j];
                csq[j] += y[j] * y[j];
            }
            size_t base = (size_t)gr * NC + colBase + tc * 8;
            *reinterpret_cast<float4*>(C + base)     = *reinterpret_cast<float4*>(y);
            *reinterpret_cast<float4*>(C + base + 4) = *reinterpret_cast<float4*>(y + 4);
        }
    }

    if (tid < BN) { s_sum[tid] = 0.f; s_sq[tid] = 0.f; }
    __syncthreads();
#pragma unroll
    for (int j = 0; j < 8; j++) {
        atomicAdd(&s_sum[tc * 8 + j], csum[j]);
        atomicAdd(&s_sq[tc * 8 + j], csq[j]);
    }
    __syncthreads();
    if (tid < BN) {
        atomicAdd(&d_stats[colBase + tid], s_sum[tid]);
        atomicAdd(&d_stats[NC + colBase + tid], s_sq[tid]);
    }
}

// ================= BN finalize (self-cleaning) =================
__global__ void finalize_kernel(const float* __restrict__ g,
                                const float* __restrict__ bt, int M, int NC) {
    int c = threadIdx.x;
    if (c < NC) {
        float invM = 1.0f / (float)M;
        float mean = d_stats[c] * invM;
        float var  = d_stats[NC + c] * invM - mean * mean;
        float sc   = g[c] * rsqrtf(var + BN_EPS);
        d_scale[c] = sc;
        d_shift[c] = bt[c] - mean * sc;
        d_stats[c] = 0.f;
        d_stats[NC + c] = 0.f;
    }
}

// ================= head =================
__global__ void head_kernel(const float* __restrict__ gm1,
                            const float* __restrict__ Wm2,
                            const float* __restrict__ bm2,
                            float* __restrict__ out) {
    __shared__ float sh[DD];
    int r = blockIdx.x;
    int t = threadIdx.x;
    float v = gm1[(size_t)r * DD + t] * d_scale[t] + d_shift[t];
    sh[t] = v > 0.f ? v : 0.f;
    __syncthreads();
    if (t < CC) {
        float acc = bm2[t];
#pragma unroll 16
        for (int k = 0; k < DD; k++) acc += sh[k] * Wm2[k * CC + t];
        out[(size_t)r * CC + t] = acc;
    }
}

extern "C" void kernel_launch(void* const* d_in, const int* in_sizes, int n_in,
                              void* d_out, int out_size) {
    const float* x    = (const float*)d_in[0];
    const int*   ei   = (const int*)d_in[1];
    const int*   batch= (const int*)d_in[2];
    const float* eps  = (const float*)d_in[3];
    const float* W1   = (const float*)d_in[4];
    const float* b1   = (const float*)d_in[5];
    const float* g1   = (const float*)d_in[6];
    const float* bt1  = (const float*)d_in[7];
    const float* W2   = (const float*)d_in[8];
    const float* b2   = (const float*)d_in[9];
    const float* g2   = (const float*)d_in[10];
    const float* bt2  = (const float*)d_in[11];
    const float* Wm1  = (const float*)d_in[12];
    const float* bm1  = (const float*)d_in[13];
    const float* gm   = (const float*)d_in[14];
    const float* btm  = (const float*)d_in[15];
    const float* Wm2  = (const float*)d_in[16];
    const float* bm2  = (const float*)d_in[17];
    float* out = (float*)d_out;

    const int* src = ei;
    const int* dst = ei + EE;

    void *countsPtr, *gePtr;
    cudaGetSymbolAddress(&countsPtr, d_counts);
    cudaGetSymbolAddress(&gePtr,     d_ge);

    float *aggPtr, *y1Ptr, *y2Ptr, *gm1Ptr;
    cudaGetSymbolAddress((void**)&aggPtr, d_agg);
    cudaGetSymbolAddress((void**)&y1Ptr,  d_y1);
    cudaGetSymbolAddress((void**)&y2Ptr,  d_y2);
    cudaGetSymbolAddress((void**)&gm1Ptr, d_gm1);

    uint32_t *pW1Hi, *pW1Md, *pW2Hi, *pW2Md;
    cudaGetSymbolAddress((void**)&pW1Hi, d_pW1Hi);
    cudaGetSymbolAddress((void**)&pW1Md, d_pW1Md);
    cudaGetSymbolAddress((void**)&pW2Hi, d_pW2Hi);
    cudaGetSymbolAddress((void**)&pW2Md, d_pW2Md);

    const int MMASMEM = 16384 * sizeof(uint32_t);   // 64 KB dynamic
    cudaFuncSetAttribute(mma_gemm_kernel<DD, H2, 2>,
                         cudaFuncAttributeMaxDynamicSharedMemorySize, MMASMEM);
    cudaFuncSetAttribute(mma_gemm_kernel<H2, DD, 1>,
                         cudaFuncAttributeMaxDynamicSharedMemorySize, MMASMEM);

    // ---- pre-pack ALL weights in ONE launch ----
    {
        dim3 pgrid(64, 8);
        packAll_kernel<<<pgrid, 256>>>(W1, W2);
    }

    // ---- CSR build ----
    cudaMemsetAsync(countsPtr, 0, NN * sizeof(int));
    hist_kernel<<<(EE + 255) / 256, 256>>>(dst);
    scan_block_kernel<<<NPART, 1024>>>();
    scan_part_kernel<<<1, 128>>>();
    scan_add_kernel<<<NPART, 1024>>>();
    fill_kernel<<<(EE + 255) / 256, 256>>>(src, dst);

    const int aggBlocks  = (NN * 32 + 255) / 256;
    const int poolBlocks = (NN * 32 + 255) / 256;
    const int gemmBlocks = (NN + 127) / 128;   // 782

    dim3 gemm1_grid(gemmBlocks, H2 / 128);
    dim3 gemm2_grid(gemmBlocks, DD / 128);
    dim3 gemmM_grid((GG + 127) / 128, DD / 128);

    for (int l = 0; l < LL; l++) {
        if (l == 0) aggregate_kernel<0><<<aggBlocks, 256>>>(x, eps + l);
        else        aggregate_kernel<1><<<aggBlocks, 256>>>(y2Ptr, eps + l);

        mma_gemm_kernel<DD, H2, 2><<<gemm1_grid, 256, MMASMEM>>>(
            aggPtr,
            (const uint4*)(pW1Hi + (size_t)l * 16384),
            (const uint4*)(pW1Md + (size_t)l * 16384),
            b1 + (size_t)l * H2, y1Ptr, NN);
        finalize_kernel<<<1, H2>>>(g1 + (size_t)l * H2, bt1 + (size_t)l * H2, NN, H2);

        mma_gemm_kernel<H2, DD, 1><<<gemm2_grid, 256, MMASMEM>>>(
            y1Ptr,
            (const uint4*)(pW2Hi + (size_t)l * 16384),
            (const uint4*)(pW2Md + (size_t)l * 16384),
            b2 + (size_t)l * DD, y2Ptr, NN);
        finalize_kernel<<<1, DD>>>(g2 + (size_t)l * DD, bt2 + (size_t)l * DD, NN, DD);
    }

    // global add pool (applies last BN2+relu inline)
    cudaMemsetAsync(gePtr, 0, (size_t)GG * DD * sizeof(float));
    pool_kernel<<<poolBlocks, 256>>>(y2Ptr, batch);

    gemm128_kernel<DD, DD, 2><<<gemmM_grid, 256>>>(
        (const float*)gePtr, Wm1, bm1, gm1Ptr, GG);
    finalize_kernel<<<1, DD>>>(gm, btm, GG, DD);

    head_kernel<<<GG, DD>>>(gm1Ptr, Wm2, bm2, out);
}

// round 16
// speedup vs baseline: 1.0077x; 1.0077x over previous
#include <cuda_runtime.h>
#include <cuda_bf16.h>
#include <math.h>
#include <stdint.h>

#define NN 100000
#define EE 3200000
#define DD 128
#define H2 256
#define LL 4
#define GG 1000
#define CC 10
#define BN_EPS 1e-5f
#define NPART 98   // ceil(NN/1024)

// -------- scratch --------
__device__ float d_agg[(size_t)NN * DD];
__device__ float d_y1 [(size_t)NN * H2];
__device__ float d_y2 [(size_t)NN * DD];
__device__ float d_ge [(size_t)GG * DD];
__device__ float d_gm1[(size_t)GG * DD];
__device__ float d_stats[2 * H2];      // zero-init; finalize self-cleans
__device__ float d_scale[H2];
__device__ float d_shift[H2];
// CSR scratch
__device__ int d_counts[NN];
__device__ int d_off[NN + 1];
__device__ int d_cur[NN];
__device__ int d_csr[EE];
__device__ int d_part[NPART];
// pre-packed weights, bf16x2 fragment order (hi/mid): per layer 16384 u32 each
__device__ uint32_t d_pW1Hi[4 * 16384];
__device__ uint32_t d_pW1Md[4 * 16384];
__device__ uint32_t d_pW2Hi[4 * 16384];
__device__ uint32_t d_pW2Md[4 * 16384];

// ================= bf16 helpers =================
static __device__ __forceinline__ void split2(float v0, float v1,
                                              uint32_t& hi, uint32_t& md) {
    __nv_bfloat16 h0 = __float2bfloat16_rn(v0);
    __nv_bfloat16 h1 = __float2bfloat16_rn(v1);
    float m0 = v0 - __bfloat162float(h0);
    float m1 = v1 - __bfloat162float(h1);
    __nv_bfloat162 hp = __halves2bfloat162(h0, h1);       // .x = lo half = k even
    __nv_bfloat162 mp = __floats2bfloat162_rn(m0, m1);
    hi = *reinterpret_cast<uint32_t*>(&hp);
    md = *reinterpret_cast<uint32_t*>(&mp);
}
static __device__ __forceinline__ void mma16(float* c, const uint32_t* a, const uint32_t* b) {
    asm volatile(
        "mma.sync.aligned.m16n8k16.row.col.f32.bf16.bf16.f32 "
        "{%0,%1,%2,%3}, {%4,%5,%6,%7}, {%8,%9}, {%0,%1,%2,%3};"
        : "+f"(c[0]), "+f"(c[1]), "+f"(c[2]), "+f"(c[3])
        : "r"(a[0]), "r"(a[1]), "r"(a[2]), "r"(a[3]), "r"(b[0]), "r"(b[1]));
}

// ======== W pre-pack (ALL layers/tensors in ONE launch) ========
// blockIdx.y in [0,8): l = y>>1; tensor = y&1 (0 -> W1 [DD,H2], 1 -> W2 [H2,DD]).
__global__ void packAll_kernel(const float* __restrict__ W1,
                               const float* __restrict__ W2) {
    int which = blockIdx.y;
    int l = which >> 1;
    int isW2 = which & 1;
    int K  = isW2 ? H2 : DD;
    int NC = isW2 ? DD : H2;
    const float* W = (isW2 ? W2 : W1) + (size_t)l * DD * H2;
    uint32_t* pHi = (isW2 ? d_pW2Hi : d_pW1Hi) + (size_t)l * 16384;
    uint32_t* pMd = (isW2 ? d_pW2Md : d_pW1Md) + (size_t)l * 16384;

    int idx = blockIdx.x * 256 + threadIdx.x;
    if (idx >= (K / 2) * NC) return;
    int k2 = idx / NC, n = idx % NC;
    int k = k2 * 2;
    float v0 = W[(size_t)k * NC + n];
    float v1 = W[(size_t)(k + 1) * NC + n];
    uint32_t hi, md;
    split2(v0, v1, hi, md);
    int colblk = n >> 7, nloc = n & 127;
    int ktile = k >> 5, kin32 = k & 31;
    int k16 = kin32 >> 4, kin16 = kin32 & 15;
    int kpair = kin16 >> 1;
    int j = kpair >> 2;
    int lane = ((nloc & 7) << 2) | (kpair & 3);
    int n8 = nloc >> 3;
    int KT = K / 32;
    size_t o = (size_t)(colblk * KT + ktile) * 2048 +
               (size_t)((k16 * 16 + n8) * 32 + lane) * 2 + j;
    pHi[o] = hi;
    pMd[o] = md;
}

// ============ bf16 2-split x3 MMA GEMM + fused BN stats, single sync per ktile ==========
// (R14 configuration — proven best)
// MODE 1: a = relu(A*scale[k]+shift[k]);  MODE 2: a = A
template <int K, int NC, int MODE>
__global__ __launch_bounds__(256) void mma_gemm_kernel(
    const float* __restrict__ A,
    const uint4* __restrict__ pWH,
    const uint4* __restrict__ pWM,
    const float* __restrict__ bias,
    float* __restrict__ C, int M)
{
    constexpr int KT = K / 32;
    extern __shared__ uint32_t smu[];
    __shared__ float s_bias[128];
    __shared__ float sScale[256];
    __shared__ float sShift[256];
    __shared__ float s_sum[128];
    __shared__ float s_sq[128];

    int tid = threadIdx.x;
    int lane = tid & 31;
    int w = tid >> 5;
    int wm = w & 3;
    int wn = w >> 2;
    int rowBase = blockIdx.x * 128;
    int colBase = blockIdx.y * 128;

    if (tid < 128) { s_bias[tid] = bias[colBase + tid]; s_sum[tid] = 0.f; s_sq[tid] = 0.f; }
    if (MODE == 1) {
        for (int c = tid; c < K; c += 256) { sScale[c] = d_scale[c]; sShift[c] = d_shift[c]; }
    }
    __syncthreads();

    float acc[2][8][4];
#pragma unroll
    for (int i = 0; i < 2; i++)
#pragma unroll
        for (int t = 0; t < 8; t++)
#pragma unroll
            for (int j = 0; j < 4; j++) acc[i][t][j] = 0.f;

    int kpairT = lane & 7;
    int k16T   = (w >> 2) & 1;
    int mLow   = (((lane >> 4) & 1) << 3) | ((w & 3) << 1) | ((lane >> 3) & 1);
    int jA     = ((kpairT >> 2) << 1) | ((lane >> 4) & 1);
    int laneA  = (((mLow & 7)) << 2) | (kpairT & 3);

    float2 aPre[8];
    uint4 bPreH[2], bPreM[2];

    auto ldgA = [&](int k0) {
        int kk = k0 + (k16T << 4) + (kpairT << 1);
#pragma unroll
        for (int e = 0; e < 8; e++) {
            int m = (e << 4) | mLow;
            aPre[e] = (rowBase + m < M)
                ? *reinterpret_cast<const float2*>(A + (size_t)(rowBase + m) * K + kk)
                : make_float2(0.f, 0.f);
        }
    };
    auto ldgB = [&](int kt) {
        size_t blkOff = (size_t)(blockIdx.y * KT + kt) * 512;
#pragma unroll
        for (int q = 0; q < 2; q++) {
            bPreH[q] = pWH[blkOff + tid + q * 256];
            bPreM[q] = pWM[blkOff + tid + q * 256];
        }
    };
    auto stsA = [&](int k0, int buf) {
        uint32_t* aHi = smu + buf * 8192;
        uint32_t* aMd = aHi + 2048;
        int kc0 = (k16T << 4) + (kpairT << 1);
#pragma unroll
        for (int e = 0; e < 8; e++) {
            float v0 = aPre[e].x, v1 = aPre[e].y;
            if (MODE == 1) {
                int kc = k0 + kc0;
                v0 = fmaxf(v0 * sScale[kc] + sShift[kc], 0.f);
                v1 = fmaxf(v1 * sScale[kc + 1] + sShift[kc + 1], 0.f);
            }
            uint32_t hi, md;
            split2(v0, v1, hi, md);
            int idx = ((k16T * 8 + e) * 32 + laneA) * 4 + jA;
            aHi[idx] = hi;
            aMd[idx] = md;
        }
    };
    auto stsB = [&](int buf) {
        uint4* bHi = reinterpret_cast<uint4*>(smu + buf * 8192 + 4096);
        uint4* bMd = reinterpret_cast<uint4*>(smu + buf * 8192 + 6144);
#pragma unroll
        for (int q = 0; q < 2; q++) {
            bHi[tid + q * 256] = bPreH[q];
            bMd[tid + q * 256] = bPreM[q];
        }
    };

    // prologue
    ldgA(0); ldgB(0);
    stsA(0, 0); stsB(0);
    __syncthreads();

    for (int kt = 0; kt < KT; kt++) {
        int buf = kt & 1;
        if (kt + 1 < KT) {
            ldgA((kt + 1) * 32);
            ldgB(kt + 1);
        }
        uint32_t* aHi = smu + buf * 8192;
        uint32_t* aMd = aHi + 2048;
        uint32_t* bHi = smu + buf * 8192 + 4096;
        uint32_t* bMd = smu + buf * 8192 + 6144;
#pragma unroll
        for (int s = 0; s < 2; s++) {
            uint32_t ah[2][4], am[2][4], bh[8][2], bm[8][2];
#pragma unroll
            for (int i = 0; i < 2; i++) {
                int base = ((s * 8 + (wm * 2 + i)) * 32 + lane) * 4;
                *reinterpret_cast<uint4*>(ah[i]) = *reinterpret_cast<const uint4*>(aHi + base);
                *reinterpret_cast<uint4*>(am[i]) = *reinterpret_cast<const uint4*>(aMd + base);
            }
#pragma unroll
            for (int t = 0; t < 8; t++) {
                int base = ((s * 16 + (wn * 8 + t)) * 32 + lane) * 2;
                *reinterpret_cast<uint2*>(bh[t]) = *reinterpret_cast<const uint2*>(bHi + base);
                *reinterpret_cast<uint2*>(bm[t]) = *reinterpret_cast<const uint2*>(bMd + base);
            }
#pragma unroll
            for (int i = 0; i < 2; i++)
#pragma unroll
                for (int t = 0; t < 8; t++) {
                    mma16(acc[i][t], ah[i], bh[t]);
                    mma16(acc[i][t], ah[i], bm[t]);
                    mma16(acc[i][t], am[i], bh[t]);
                }
        }
        // single barrier per ktile: writes go to buf^1, whose last readers
        // finished before the PREVIOUS barrier.
        if (kt + 1 < KT) {
            stsA((kt + 1) * 32, buf ^ 1);
            stsB(buf ^ 1);
            __syncthreads();
        }
    }

    // epilogue + fused column stats
    int g = lane >> 2, tq = lane & 3;
    float csum[16], csq[16];
#pragma unroll
    for (int t = 0; t < 16; t++) { csum[t] = 0.f; csq[t] = 0.f; }

#pragma unroll
    for (int i = 0; i < 2; i++) {
        int r0 = rowBase + wm * 32 + i * 16 + g;
#pragma unroll
        for (int t = 0; t < 8; t++) {
            int cloc = wn * 64 + t * 8 + 2 * tq;
            int cg = colBase + cloc;
            float b0 = s_bias[cloc], b1 = s_bias[cloc + 1];
            if (r0 < M) {
                float y0 = acc[i][t][0] + b0, y1 = acc[i][t][1] + b1;
                *reinterpret_cast<float2*>(C + (size_t)r0 * NC + cg) = make_float2(y0, y1);
                csum[2 * t] += y0; csq[2 * t] += y0 * y0;
                csum[2 * t + 1] += y1; csq[2 * t + 1] += y1 * y1;
            }
            if (r0 + 8 < M) {
                float y2 = acc[i][t][2] + b0, y3 = acc[i][t][3] + b1;
                *reinterpret_cast<float2*>(C + (size_t)(r0 + 8) * NC + cg) = make_float2(y2, y3);
                csum[2 * t] += y2; csq[2 * t] += y2 * y2;
                csum[2 * t + 1] += y3; csq[2 * t + 1] += y3 * y3;
            }
        }
    }
#pragma unroll
    for (int t = 0; t < 8; t++) {
        int cloc = wn * 64 + t * 8 + 2 * tq;
        atomicAdd(&s_sum[cloc], csum[2 * t]);
        atomicAdd(&s_sq[cloc], csq[2 * t]);
        atomicAdd(&s_sum[cloc + 1], csum[2 * t + 1]);
        atomicAdd(&s_sq[cloc + 1], csq[2 * t + 1]);
    }
    __syncthreads();
    if (tid < 128) {
        atomicAdd(&d_stats[colBase + tid], s_sum[tid]);
        atomicAdd(&d_stats[NC + colBase + tid], s_sq[tid]);
    }
}

// ================= CSR build =================
__global__ void hist_kernel(const int* __restrict__ dst) {
    int e = blockIdx.x * blockDim.x + threadIdx.x;
    if (e < EE) atomicAdd(&d_counts[dst[e]], 1);
}

__global__ void scan_block_kernel() {
    __shared__ int sm[1024];
    int b = blockIdx.x, t = threadIdx.x;
    int i = b * 1024 + t;
    sm[t] = (i < NN) ? d_counts[i] : 0;
    __syncthreads();
    for (int s = 1; s < 1024; s <<= 1) {
        int a = (t >= s) ? sm[t - s] : 0;
        __syncthreads();
        sm[t] += a;
        __syncthreads();
    }
    if (i < NN) d_off[i + 1] = sm[t];
    if (t == 1023) d_part[b] = sm[1023];
}

__global__ void scan_part_kernel() {
    __shared__ int sm[128];
    int t = threadIdx.x;
    sm[t] = (t < NPART) ? d_part[t] : 0;
    __syncthreads();
    for (int s = 1; s < 128; s <<= 1) {
        int a = (t >= s) ? sm[t - s] : 0;
        __syncthreads();
        sm[t] += a;
        __syncthreads();
    }
    if (t < NPART) d_part[t] = sm[t];
    if (t == 0) { d_off[0] = 0; d_cur[0] = 0; }
}

__global__ void scan_add_kernel() {
    int b = blockIdx.x, t = threadIdx.x;
    int i = b * 1024 + t;
    if (i < NN) {
        int add = (b > 0) ? d_part[b - 1] : 0;
        int v = d_off[i + 1] + add;
        d_off[i + 1] = v;
        if (i + 1 < NN) d_cur[i + 1] = v;
    }
}

__global__ void fill_kernel(const int* __restrict__ src, const int* __restrict__ dst) {
    int e = blockIdx.x * blockDim.x + threadIdx.x;
    if (e < EE) {
        int d = dst[e];
        int p = atomicAdd(&d_cur[d], 1);
        d_csr[p] = src[e];
    }
}

// ========== aggregation with optional fused BN+relu on the gathered input ==========
template <int MODE>
__global__ void aggregate_kernel(const float* __restrict__ h,
                                 const float* __restrict__ epsp) {
    int gt = blockIdx.x * blockDim.x + threadIdx.x;
    int n = gt >> 5;
    int lane = gt & 31;
    if (n >= NN) return;
    float4 sc, sf;
    if (MODE == 1) {
        sc = *reinterpret_cast<const float4*>(d_scale + lane * 4);
        sf = *reinterpret_cast<const float4*>(d_shift + lane * 4);
    }
    int beg = d_off[n], end = d_off[n + 1];
    float4 acc = make_float4(0.f, 0.f, 0.f, 0.f);
    const float* hl = h + (size_t)lane * 4;

    auto fetch = [&](int node) -> float4 {
        float4 v = *reinterpret_cast<const float4*>(hl + (size_t)node * DD);
        if (MODE == 1) {
            v.x = fmaxf(v.x * sc.x + sf.x, 0.f);
            v.y = fmaxf(v.y * sc.y + sf.y, 0.f);
            v.z = fmaxf(v.z * sc.z + sf.z, 0.f);
            v.w = fmaxf(v.w * sc.w + sf.w, 0.f);
        }
        return v;
    };

    int i = beg;
    for (; i + 4 <= end; i += 4) {
        float4 v0 = fetch(d_csr[i]);
        float4 v1 = fetch(d_csr[i + 1]);
        float4 v2 = fetch(d_csr[i + 2]);
        float4 v3 = fetch(d_csr[i + 3]);
        acc.x += (v0.x + v1.x) + (v2.x + v3.x);
        acc.y += (v0.y + v1.y) + (v2.y + v3.y);
        acc.z += (v0.z + v1.z) + (v2.z + v3.z);
        acc.w += (v0.w + v1.w) + (v2.w + v3.w);
    }
    for (; i < end; i++) {
        float4 v0 = fetch(d_csr[i]);
        acc.x += v0.x; acc.y += v0.y; acc.z += v0.z; acc.w += v0.w;
    }
    float e = 1.0f + epsp[0];
    float4 self = fetch(n);
    acc.x += e * self.x; acc.y += e * self.y;
    acc.z += e * self.z; acc.w += e * self.w;
    *reinterpret_cast<float4*>(d_agg + (size_t)n * DD + lane * 4) = acc;
}

// ================= pool with fused BN+relu (reads y2) =================
__global__ void pool_kernel(const float* __restrict__ y2,
                            const int* __restrict__ batch) {
    int gt = blockIdx.x * blockDim.x + threadIdx.x;
    int n = gt >> 5;
    int lane = gt & 31;
    if (n >= NN) return;
    float4 sc = *reinterpret_cast<const float4*>(d_scale + lane * 4);
    float4 sf = *reinterpret_cast<const float4*>(d_shift + lane * 4);
    int g = batch[n];
    float4 v = *reinterpret_cast<const float4*>(y2 + (size_t)n * DD + lane * 4);
    v.x = fmaxf(v.x * sc.x + sf.x, 0.f);
    v.y = fmaxf(v.y * sc.y + sf.y, 0.f);
    v.z = fmaxf(v.z * sc.z + sf.z, 0.f);
    v.w = fmaxf(v.w * sc.w + sf.w, 0.f);
    atomicAdd(reinterpret_cast<float4*>(d_ge + (size_t)g * DD + lane * 4), v);
}

// ================= SIMT GEMM (head only; fused stats) =================
template <int K, int NC, int MODE>
__global__ __launch_bounds__(256, 2) void gemm128_kernel(
    const float* __restrict__ A,
    const float* __restrict__ W,
    const float* __restrict__ bias,
    float* __restrict__ C, int M)
{
    constexpr int BM = 128, BN = 128, BK = 16;
    constexpr int KT = K / BK;
    __shared__ float As[2][BK][BM + 4];
    __shared__ float Bs[2][BK][BN];
    __shared__ float s_sum[BN];
    __shared__ float s_sq[BN];

    int tid = threadIdx.x;
    int tr = tid >> 4;
    int tc = tid & 15;
    int rowBase = blockIdx.x * BM;
    int colBase = blockIdx.y * BN;

    float acc[8][8];
#pragma unroll
    for (int i = 0; i < 8; i++)
#pragma unroll
        for (int j = 0; j < 8; j++) acc[i][j] = 0.f;

    float4 a_reg[2], b_reg[2];

    auto loadA = [&](int k0, int q) -> float4 {
        int fIdx = tid + q * 256;
        int m = fIdx >> 2;
        int kq = (fIdx & 3) << 2;
        int gr = rowBase + m;
        float4 v = make_float4(0.f, 0.f, 0.f, 0.f);
        if (gr < M) v = *reinterpret_cast<const float4*>(A + (size_t)gr * K + k0 + kq);
        return v;
    };
    auto loadB = [&](int k0, int q) -> float4 {
        int fIdx = tid + q * 256;
        int kk = fIdx >> 5;
        int n4 = (fIdx & 31) << 2;
        return *reinterpret_cast<const float4*>(W + (size_t)(k0 + kk) * NC + colBase + n4);
    };
    auto storeA = [&](int buf, int q, float4 v) {
        int fIdx = tid + q * 256;
        int m = fIdx >> 2;
        int kq = (fIdx & 3) << 2;
        As[buf][kq + 0][m] = v.x;
        As[buf][kq + 1][m] = v.y;
        As[buf][kq + 2][m] = v.z;
        As[buf][kq + 3][m] = v.w;
    };
    auto storeB = [&](int buf, int q, float4 v) {
        int fIdx = tid + q * 256;
        int kk = fIdx >> 5;
        int n4 = (fIdx & 31) << 2;
        *reinterpret_cast<float4*>(&Bs[buf][kk][n4]) = v;
    };

    a_reg[0] = loadA(0, 0); a_reg[1] = loadA(0, 1);
    b_reg[0] = loadB(0, 0); b_reg[1] = loadB(0, 1);
    storeA(0, 0, a_reg[0]); storeA(0, 1, a_reg[1]);
    storeB(0, 0, b_reg[0]); storeB(0, 1, b_reg[1]);
    __syncthreads();

    for (int kt = 0; kt < KT; kt++) {
        int buf = kt & 1;
        if (kt + 1 < KT) {
            int k0 = (kt + 1) * BK;
            a_reg[0] = loadA(k0, 0); a_reg[1] = loadA(k0, 1);
            b_reg[0] = loadB(k0, 0); b_reg[1] = loadB(k0, 1);
        }
#pragma unroll
        for (int kk = 0; kk < BK; kk++) {
            float ra[8], rb[8];
            *reinterpret_cast<float4*>(ra)     = *reinterpret_cast<const float4*>(&As[buf][kk][tr * 8]);
            *reinterpret_cast<float4*>(ra + 4) = *reinterpret_cast<const float4*>(&As[buf][kk][tr * 8 + 4]);
            *reinterpret_cast<float4*>(rb)     = *reinterpret_cast<const float4*>(&Bs[buf][kk][tc * 8]);
            *reinterpret_cast<float4*>(rb + 4) = *reinterpret_cast<const float4*>(&Bs[buf][kk][tc * 8 + 4]);
#pragma unroll
            for (int i = 0; i < 8; i++)
#pragma unroll
                for (int j = 0; j < 8; j++) acc[i][j] += ra[i] * rb[j];
        }
        if (kt + 1 < KT) {
            storeA(buf ^ 1, 0, a_reg[0]); storeA(buf ^ 1, 1, a_reg[1]);
            storeB(buf ^ 1, 0, b_reg[0]); storeB(buf ^ 1, 1, b_reg[1]);
        }
        __syncthreads();
    }

    float bj[8];
#pragma unroll
    for (int j = 0; j < 8; j++) bj[j] = bias[colBase + tc * 8 + j];

    float csum[8], csq[8];
#pragma unroll
    for (int j = 0; j < 8; j++) { csum[j] = 0.f; csq[j] = 0.f; }

#pragma unroll
    for (int i = 0; i < 8; i++) {
        int gr = rowBase + tr * 8 + i;
        if (gr < M) {
            float y[8];
#pragma unroll
            for (int j = 0; j < 8; j++) {
                y[j] = acc[i][j] + bj[j];
                csum[j] += y[j];
                csq[j] += y[j] * y[j];
            }
            size_t base = (size_t)gr * NC + colBase + tc * 8;
            *reinterpret_cast<float4*>(C + base)     = *reinterpret_cast<float4*>(y);
            *reinterpret_cast<float4*>(C + base + 4) = *reinterpret_cast<float4*>(y + 4);
        }
    }

    if (tid < BN) { s_sum[tid] = 0.f; s_sq[tid] = 0.f; }
    __syncthreads();
#pragma unroll
    for (int j = 0; j < 8; j++) {
        atomicAdd(&s_sum[tc * 8 + j], csum[j]);
        atomicAdd(&s_sq[tc * 8 + j], csq[j]);
    }
    __syncthreads();
    if (tid < BN) {
        atomicAdd(&d_stats[colBase + tid], s_sum[tid]);
        atomicAdd(&d_stats[NC + colBase + tid], s_sq[tid]);
    }
}

// ================= BN finalize (self-cleaning) =================
__global__ void finalize_kernel(const float* __restrict__ g,
                                const float* __restrict__ bt, int M, int NC) {
    int c = threadIdx.x;
    if (c < NC) {
        float invM = 1.0f / (float)M;
        float mean = d_stats[c] * invM;
        float var  = d_stats[NC + c] * invM - mean * mean;
        float sc   = g[c] * rsqrtf(var + BN_EPS);
        d_scale[c] = sc;
        d_shift[c] = bt[c] - mean * sc;
        d_stats[c] = 0.f;
        d_stats[NC + c] = 0.f;
    }
}

// ================= head =================
__global__ void head_kernel(const float* __restrict__ gm1,
                            const float* __restrict__ Wm2,
                            const float* __restrict__ bm2,
                            float* __restrict__ out) {
    __shared__ float sh[DD];
    int r = blockIdx.x;
    int t = threadIdx.x;
    float v = gm1[(size_t)r * DD + t] * d_scale[t] + d_shift[t];
    sh[t] = v > 0.f ? v : 0.f;
    __syncthreads();
    if (t < CC) {
        float acc = bm2[t];
#pragma unroll 16
        for (int k = 0; k < DD; k++) acc += sh[k] * Wm2[k * CC + t];
        out[(size_t)r * CC + t] = acc;
    }
}

extern "C" void kernel_launch(void* const* d_in, const int* in_sizes, int n_in,
                              void* d_out, int out_size) {
    const float* x    = (const float*)d_in[0];
    const int*   ei   = (const int*)d_in[1];
    const int*   batch= (const int*)d_in[2];
    const float* eps  = (const float*)d_in[3];
    const float* W1   = (const float*)d_in[4];
    const float* b1   = (const float*)d_in[5];
    const float* g1   = (const float*)d_in[6];
    const float* bt1  = (const float*)d_in[7];
    const float* W2   = (const float*)d_in[8];
    const float* b2   = (const float*)d_in[9];
    const float* g2   = (const float*)d_in[10];
    const float* bt2  = (const float*)d_in[11];
    const float* Wm1  = (const float*)d_in[12];
    const float* bm1  = (const float*)d_in[13];
    const float* gm   = (const float*)d_in[14];
    const float* btm  = (const float*)d_in[15];
    const float* Wm2  = (const float*)d_in[16];
    const float* bm2  = (const float*)d_in[17];
    float* out = (float*)d_out;

    const int* src = ei;
    const int* dst = ei + EE;

    void *countsPtr, *gePtr;
    cudaGetSymbolAddress(&countsPtr, d_counts);
    cudaGetSymbolAddress(&gePtr,     d_ge);

    float *aggPtr, *y1Ptr, *y2Ptr, *gm1Ptr;
    cudaGetSymbolAddress((void**)&aggPtr, d_agg);
    cudaGetSymbolAddress((void**)&y1Ptr,  d_y1);
    cudaGetSymbolAddress((void**)&y2Ptr,  d_y2);
    cudaGetSymbolAddress((void**)&gm1Ptr, d_gm1);

    uint32_t *pW1Hi, *pW1Md, *pW2Hi, *pW2Md;
    cudaGetSymbolAddress((void**)&pW1Hi, d_pW1Hi);
    cudaGetSymbolAddress((void**)&pW1Md, d_pW1Md);
    cudaGetSymbolAddress((void**)&pW2Hi, d_pW2Hi);
    cudaGetSymbolAddress((void**)&pW2Md, d_pW2Md);

    const int MMASMEM = 16384 * sizeof(uint32_t);   // 64 KB dynamic
    cudaFuncSetAttribute(mma_gemm_kernel<DD, H2, 2>,
                         cudaFuncAttributeMaxDynamicSharedMemorySize, MMASMEM);
    cudaFuncSetAttribute(mma_gemm_kernel<H2, DD, 1>,
                         cudaFuncAttributeMaxDynamicSharedMemorySize, MMASMEM);

    // ---- pre-pack ALL weights in ONE launch ----
    {
        dim3 pgrid(64, 8);
        packAll_kernel<<<pgrid, 256>>>(W1, W2);
    }

    // ---- CSR build ----
    cudaMemsetAsync(countsPtr, 0, NN * sizeof(int));
    hist_kernel<<<(EE + 255) / 256, 256>>>(dst);
    scan_block_kernel<<<NPART, 1024>>>();
    scan_part_kernel<<<1, 128>>>();
    scan_add_kernel<<<NPART, 1024>>>();
    fill_kernel<<<(EE + 255) / 256, 256>>>(src, dst);

    const int aggBlocks  = (NN * 32 + 255) / 256;
    const int poolBlocks = (NN * 32 + 255) / 256;
    const int gemmBlocks = (NN + 127) / 128;   // 782

    dim3 gemm1_grid(gemmBlocks, H2 / 128);
    dim3 gemm2_grid(gemmBlocks, DD / 128);
    dim3 gemmM_grid((GG + 127) / 128, DD / 128);

    for (int l = 0; l < LL; l++) {
        if (l == 0) aggregate_kernel<0><<<aggBlocks, 256>>>(x, eps + l);
        else        aggregate_kernel<1><<<aggBlocks, 256>>>(y2Ptr, eps + l);

        mma_gemm_kernel<DD, H2, 2><<<gemm1_grid, 256, MMASMEM>>>(
            aggPtr,
            (const uint4*)(pW1Hi + (size_t)l * 16384),
            (const uint4*)(pW1Md + (size_t)l * 16384),
            b1 + (size_t)l * H2, y1Ptr, NN);
        finalize_kernel<<<1, H2>>>(g1 + (size_t)l * H2, bt1 + (size_t)l * H2, NN, H2);

        mma_gemm_kernel<H2, DD, 1><<<gemm2_grid, 256, MMASMEM>>>(
            y1Ptr,
            (const uint4*)(pW2Hi + (size_t)l * 16384),
            (const uint4*)(pW2Md + (size_t)l * 16384),
            b2 + (size_t)l * DD, y2Ptr, NN);
        finalize_kernel<<<1, DD>>>(g2 + (size_t)l * DD, bt2 + (size_t)l * DD, NN, DD);
    }

    // global add pool (applies last BN2+relu inline)
    cudaMemsetAsync(gePtr, 0, (size_t)GG * DD * sizeof(float));
    pool_kernel<<<poolBlocks, 256>>>(y2Ptr, batch);

    gemm128_kernel<DD, DD, 2><<<gemmM_grid, 256>>>(
        (const float*)gePtr, Wm1, bm1, gm1Ptr, GG);
    finalize_kernel<<<1, DD>>>(gm, btm, GG, DD);

    head_kernel<<<GG, DD>>>(gm1Ptr, Wm2, bm2, out);
}